// round 3
// baseline (speedup 1.0000x reference)
#include <cuda_runtime.h>
#include <cstdint>
#include <math.h>

#define NB 4096
#define NSUP 5
#define NROWS (NB + NSUP)   // 4101
#define ED 128
#define DM 256
#define DI 512
#define LH 512
#define G4 2048
#define PADI 200000
#define MAXK 64
#define TOPK 10

// ------------------- device scratch -------------------
__device__ float g_vec[NROWS * DM];
__device__ float g_h1[NROWS * DI];
__device__ float g_enc[NROWS * DM];
__device__ float g_supg[DM];
__device__ float g_rpart[G4];
__device__ float g_bsum[G4];
__device__ float g_xpart[(size_t)NB * G4];
__device__ float g_gates[(size_t)NB * G4];
__device__ float g_h[(size_t)NB * DM];
__device__ float g_c[(size_t)NB * LH];
__device__ float g_gcnWt[DM * ED];
// tf32-pre-rounded weight copies
__device__ float g_wihR[G4 * DM];
__device__ float g_whhR[G4 * LH];
__device__ float g_p1R[DI * DM];
__device__ float g_p2R[DM * DI];

__device__ __forceinline__ float warp_sum(float v) {
#pragma unroll
    for (int o = 16; o; o >>= 1) v += __shfl_xor_sync(0xffffffffu, v, o);
    return v;
}
__device__ __forceinline__ float sigf(float x) { return 1.0f / (1.0f + expf(-x)); }
__device__ __forceinline__ float tf32r(float v) {
    uint32_t r;
    asm("cvt.rna.tf32.f32 %0, %1;" : "=r"(r) : "f"(v));
    return __uint_as_float(r);
}

// ------------------- prep: transpose gcn W, sum biases -------------------
__global__ void prep_kernel(const float* __restrict__ gcn_w_w,
                            const float* __restrict__ b_ih,
                            const float* __restrict__ b_hh) {
    int t = threadIdx.x;
    if (blockIdx.x < 128) {
        int d = blockIdx.x;
        g_gcnWt[t * ED + d] = gcn_w_w[d * DM + t];
    } else {
        int n = (blockIdx.x - 128) * 256 + t;
        g_bsum[n] = b_ih[n] + b_hh[n];
    }
}

// round a weight matrix to tf32 into a device copy
__global__ void round_kernel(const float* __restrict__ src, float* __restrict__ dst, int n) {
    int i = blockIdx.x * 256 + threadIdx.x;
    if (i < n) dst[i] = tf32r(src[i]);
}

// ------------------- neighbor encoder -------------------
__global__ void __launch_bounds__(128)
neighbor_kernel(const int* __restrict__ qry, const int* __restrict__ sup,
                const int* __restrict__ q_l1, const int* __restrict__ q_deg_l,
                const int* __restrict__ q_r1, const int* __restrict__ q_deg_r,
                const int* __restrict__ s_l1, const int* __restrict__ s_deg_l,
                const int* __restrict__ s_r1, const int* __restrict__ s_deg_r,
                const float* __restrict__ emb,
                const float* __restrict__ gcn_w_b, const float* __restrict__ gcn_b,
                const float* __restrict__ g1_w, const float* __restrict__ g1_b,
                const float* __restrict__ ln1_g, const float* __restrict__ ln1_b,
                const float* __restrict__ g2_w, const float* __restrict__ g2_b,
                const float* __restrict__ gate_temp) {
    __shared__ float s_self[ED], s_selfn[ED];
    __shared__ float s_sim[MAXK];
    __shared__ int s_rel[MAXK], s_ent[MAXK];
    __shared__ int s_sel[TOPK], s_pad[TOPK];
    __shared__ float s_concat[TOPK * DM];
    __shared__ float s_agg[ED];
    __shared__ float s_red[8];
    __shared__ float s_sc[2];
    __shared__ int s_nv;

    int blk = blockIdx.x, tid = threadIdx.x;
    const int* conn;
    int selfid, deg;
    float* out;
    if (blk < NB) {
        int b = blk; conn = q_l1 + b * MAXK * 2; deg = q_deg_l[b];
        selfid = qry[b * 2 + 0]; out = g_vec + (size_t)b * DM;
    } else if (blk < 2 * NB) {
        int b = blk - NB; conn = q_r1 + b * MAXK * 2; deg = q_deg_r[b];
        selfid = qry[b * 2 + 1]; out = g_vec + (size_t)b * DM + ED;
    } else if (blk < 2 * NB + NSUP) {
        int i = blk - 2 * NB; conn = s_l1 + i * MAXK * 2; deg = s_deg_l[i];
        selfid = sup[i * 2 + 0]; out = g_vec + (size_t)(NB + i) * DM;
    } else {
        int i = blk - 2 * NB - NSUP; conn = s_r1 + i * MAXK * 2; deg = s_deg_r[i];
        selfid = sup[i * 2 + 1]; out = g_vec + (size_t)(NB + i) * DM + ED;
    }

    float se = emb[(size_t)selfid * ED + tid];
    s_self[tid] = se;
    float ss = warp_sum(se * se);
    if ((tid & 31) == 0) s_red[tid >> 5] = ss;
    __syncthreads();
    if (tid == 0)
        s_sc[0] = 1.0f / fmaxf(sqrtf(s_red[0] + s_red[1] + s_red[2] + s_red[3]), 1e-12f);
    __syncthreads();
    s_selfn[tid] = se * s_sc[0];
    __syncthreads();

    int warp = tid >> 5, lane = tid & 31;
    float4 sn = ((const float4*)s_selfn)[lane];
    for (int j = warp; j < MAXK; j += 4) {
        int rel = conn[j * 2 + 0];
        int ent = conn[j * 2 + 1];
        float4 e = ((const float4*)(emb + (size_t)ent * ED))[lane];
        float dot = e.x * sn.x + e.y * sn.y + e.z * sn.z + e.w * sn.w;
        float sq = e.x * e.x + e.y * e.y + e.z * e.z + e.w * e.w;
        dot = warp_sum(dot);
        sq = warp_sum(sq);
        if (lane == 0) {
            float sim = dot / fmaxf(sqrtf(sq), 1e-12f);
            if (rel == PADI) sim -= 1e9f;
            s_sim[j] = sim; s_rel[j] = rel; s_ent[j] = ent;
        }
    }
    __syncthreads();

    // warp-parallel top-10 (ties -> lowest index, matching jax.lax.top_k)
    if (warp == 0) {
        float v0 = s_sim[lane], v1 = s_sim[lane + 32];
        int nv = 0;
#pragma unroll
        for (int t = 0; t < TOPK; t++) {
            float mv = v0; int mi = lane;
            if (v1 > mv) { mv = v1; mi = lane + 32; }
#pragma unroll
            for (int o = 16; o; o >>= 1) {
                float ov = __shfl_xor_sync(0xffffffffu, mv, o);
                int oi = __shfl_xor_sync(0xffffffffu, mi, o);
                if (ov > mv || (ov == mv && oi < mi)) { mv = ov; mi = oi; }
            }
            if (lane == 0) {
                s_sel[t] = mi;
                int p = (s_rel[mi] == PADI);
                s_pad[t] = p;
                if (!p) nv++;
            }
            if (mi == lane) v0 = -3.0e38f;
            if (mi == lane + 32) v1 = -3.0e38f;
        }
        if (lane == 0) s_nv = nv;
    }
    __syncthreads();

    for (int t = tid; t < TOPK * DM; t += 128) {
        int j = t >> 8, k = t & 255;
        int id = (k < ED) ? s_rel[s_sel[j]] : s_ent[s_sel[j]];
        s_concat[t] = emb[(size_t)id * ED + (k & (ED - 1))];
    }
    __syncthreads();

    float acc[TOPK];
#pragma unroll
    for (int j = 0; j < TOPK; j++) acc[j] = 0.f;
    for (int k0 = 0; k0 < DM; k0 += 8) {
        float w[8];
#pragma unroll
        for (int i = 0; i < 8; i++) w[i] = g_gcnWt[(k0 + i) * ED + tid];
#pragma unroll
        for (int j = 0; j < TOPK; j++) {
            float4 c0 = *(const float4*)&s_concat[j * DM + k0];
            float4 c1 = *(const float4*)&s_concat[j * DM + k0 + 4];
            acc[j] += c0.x * w[0] + c0.y * w[1] + c0.z * w[2] + c0.w * w[3]
                    + c1.x * w[4] + c1.y * w[5] + c1.z * w[6] + c1.w * w[7];
        }
    }
    float bias = gcn_w_b[tid] + gcn_b[tid];
    float agg = 0.f;
#pragma unroll
    for (int j = 0; j < TOPK; j++) {
        float v = acc[j] + bias;
        v = v > 0.f ? v : 0.01f * v;
        if (!s_pad[j]) agg += v;
    }
    agg /= fmaxf((float)s_nv, 1.0f);
    s_agg[tid] = agg;
    __syncthreads();

    float y = 0.f;
    if (tid < 64) {
        const float4* wr = (const float4*)(g1_w + tid * ED);
        const float4* ag = (const float4*)s_agg;
#pragma unroll
        for (int k = 0; k < 32; k++) {
            float4 a = ag[k]; float4 w = wr[k];
            y += a.x * w.x + a.y * w.y + a.z * w.z + a.w * w.w;
        }
        y += g1_b[tid];
    }
    float s1 = warp_sum(tid < 64 ? y : 0.f);
    float s2 = warp_sum(tid < 64 ? y * y : 0.f);
    __syncthreads();
    if ((tid & 31) == 0) { s_red[tid >> 5] = s1; s_red[4 + (tid >> 5)] = s2; }
    __syncthreads();
    float S1 = s_red[0] + s_red[1] + s_red[2] + s_red[3];
    float S2 = s_red[4] + s_red[5] + s_red[6] + s_red[7];
    float mean = S1 * (1.0f / 64.0f);
    float var = S2 * (1.0f / 64.0f) - mean * mean;
    float hv = 0.f;
    if (tid < 64) {
        hv = (y - mean) * rsqrtf(var + 1e-5f) * ln1_g[tid] + ln1_b[tid];
        hv = fmaxf(hv, 0.f);
    }
    float lz = warp_sum(tid < 64 ? hv * g2_w[tid] : 0.f);
    __syncthreads();
    if ((tid & 31) == 0) s_red[tid >> 5] = lz;
    __syncthreads();
    if (tid == 0) {
        float logit = s_red[0] + s_red[1] + s_red[2] + s_red[3] + g2_b[0];
        float temp = fminf(fmaxf(gate_temp[0], 0.1f), 5.0f);
        float gate = 1.0f / (1.0f + expf(-logit / temp));
        if (deg <= 0) gate = 0.f;
        s_sc[1] = gate;
    }
    __syncthreads();
    out[tid] = tf32r(tanhf(s_self[tid] + s_sc[1] * s_agg[tid]));
}

// ------------------- TF32 GEMM v2: fragment-order smem, register staging -------------------
// C = A(MxK) * W(NxK)^T, operands pre-rounded to tf32. BN=128 fixed, BK=16.
// BMT in {128, 64}. 256 threads, 8 warps (2 x 4), warp tile (BMT/2) x 32.
__device__ __forceinline__ void mma_tf32(float* c, const uint32_t* a, const uint32_t* b) {
    asm volatile(
        "mma.sync.aligned.m16n8k8.row.col.f32.tf32.tf32.f32 "
        "{%0,%1,%2,%3}, {%4,%5,%6,%7}, {%8,%9}, {%0,%1,%2,%3};"
        : "+f"(c[0]), "+f"(c[1]), "+f"(c[2]), "+f"(c[3])
        : "r"(a[0]), "r"(a[1]), "r"(a[2]), "r"(a[3]), "r"(b[0]), "r"(b[1]));
}

template<int BMT>
__global__ void __launch_bounds__(256, 2)
gemm_v2(const float* __restrict__ A, int lda,
        const float* __restrict__ W, int ldw,
        const float* __restrict__ bias,
        const float* __restrict__ base,
        const float* __restrict__ rowv,
        float* __restrict__ C, int ldc,
        int M, int N, int K, int act, int roundOut) {
    constexpr int AMT = BMT / 32;   // 16-row m-tiles per warp
    constexpr int NA4 = BMT / 64;   // float4 staging units per thread (A)
    __shared__ float smA[2][BMT * 16];
    __shared__ float smB[2][2048];

    const int tid = threadIdx.x;
    const int lane = tid & 31, warp = tid >> 5;
    const int wm = warp >> 2, wn = warp & 3;
    const int m0 = blockIdx.y * BMT, n0 = blockIdx.x * 128;
    const int r = lane >> 2, cq = lane & 3;
    // read-side swizzled granule (same formula as write side with g = lane)
    const int gsw = (lane & ~3) | ((lane & 3) ^ ((lane >> 3) & 3));

    const int stRow = tid >> 2;     // staging row within 64-row chunk
    const int stKg = tid & 3;       // 4-float k-group
    const int stKb = stKg >> 1, stKhi = stKg & 1;

    float4 ra[NA4], rb[2];
    float acc[AMT][4][4];
#pragma unroll
    for (int i = 0; i < AMT; i++)
#pragma unroll
        for (int j = 0; j < 4; j++)
#pragma unroll
            for (int q = 0; q < 4; q++) acc[i][j][q] = 0.f;

    const int KT = K >> 4;

    // ---- stage tile 0 ----
#pragma unroll
    for (int p = 0; p < NA4; p++) {
        int m = m0 + p * 64 + stRow;
        ra[p] = (m < M) ? *(const float4*)(A + (size_t)m * lda + stKg * 4)
                        : make_float4(0.f, 0.f, 0.f, 0.f);
    }
#pragma unroll
    for (int p = 0; p < 2; p++)
        rb[p] = *(const float4*)(W + (size_t)(n0 + p * 64 + stRow) * ldw + stKg * 4);

    auto sts = [&](int buf) {
#pragma unroll
        for (int p = 0; p < NA4; p++) {
            int row = p * 64 + stRow;
            int mb = row >> 4, rr = row & 7, hi = (row >> 3) & 1;
            float* dst = &smA[buf][(mb * 2 + stKb) * 128 + hi + 2 * stKhi];
            float v[4] = {ra[p].x, ra[p].y, ra[p].z, ra[p].w};
#pragma unroll
            for (int c = 0; c < 4; c++) {
                int g = 4 * rr + c;
                int g2 = (g & ~3) | ((g & 3) ^ ((g >> 3) & 3));
                dst[g2 * 4] = v[c];
            }
        }
#pragma unroll
        for (int p = 0; p < 2; p++) {
            int row = p * 64 + stRow;
            int nb = row >> 3, rr = row & 7;
            float* dst = &smB[buf][(nb * 2 + stKb) * 64 + stKhi];
            float v[4] = {rb[p].x, rb[p].y, rb[p].z, rb[p].w};
#pragma unroll
            for (int c = 0; c < 4; c++) {
                int g = 4 * rr + c;
                int g2 = (g & ~3) | ((g & 3) ^ ((g >> 3) & 3));
                dst[g2 * 2] = v[c];
            }
        }
    };

    sts(0);
    __syncthreads();

    int buf = 0;
    for (int kt = 0; kt < KT; kt++) {
        const bool more = (kt + 1 < KT);
        if (more) {
            int koff = (kt + 1) * 16 + stKg * 4;
#pragma unroll
            for (int p = 0; p < NA4; p++) {
                int m = m0 + p * 64 + stRow;
                ra[p] = (m < M) ? *(const float4*)(A + (size_t)m * lda + koff)
                                : make_float4(0.f, 0.f, 0.f, 0.f);
            }
#pragma unroll
            for (int p = 0; p < 2; p++)
                rb[p] = *(const float4*)(W + (size_t)(n0 + p * 64 + stRow) * ldw + koff);
        }
        // compute current tile
#pragma unroll
        for (int kb = 0; kb < 2; kb++) {
            uint32_t af[AMT][4];
#pragma unroll
            for (int am = 0; am < AMT; am++) {
                float4 t = *(const float4*)&smA[buf][((wm * AMT + am) * 2 + kb) * 128 + gsw * 4];
                af[am][0] = __float_as_uint(t.x);
                af[am][1] = __float_as_uint(t.y);
                af[am][2] = __float_as_uint(t.z);
                af[am][3] = __float_as_uint(t.w);
            }
            uint32_t bf[4][2];
#pragma unroll
            for (int an = 0; an < 4; an++) {
                float2 t = *(const float2*)&smB[buf][((wn * 4 + an) * 2 + kb) * 64 + gsw * 2];
                bf[an][0] = __float_as_uint(t.x);
                bf[an][1] = __float_as_uint(t.y);
            }
#pragma unroll
            for (int am = 0; am < AMT; am++)
#pragma unroll
                for (int an = 0; an < 4; an++)
                    mma_tf32(acc[am][an], af[am], bf[an]);
        }
        if (more) sts(buf ^ 1);
        __syncthreads();
        buf ^= 1;
    }

    // ---- epilogue ----
#pragma unroll
    for (int am = 0; am < AMT; am++) {
        int row0 = m0 + wm * (AMT * 16) + am * 16 + r;
        int row1 = row0 + 8;
#pragma unroll
        for (int an = 0; an < 4; an++) {
            int col = n0 + wn * 32 + an * 8 + cq * 2;
            float add0 = 0.f, add1 = 0.f;
            if (bias) { add0 += bias[col]; add1 += bias[col + 1]; }
            if (rowv) { add0 += rowv[col]; add1 += rowv[col + 1]; }
            if (row0 < M) {
                float v0 = acc[am][an][0] + add0;
                float v1 = acc[am][an][1] + add1;
                if (base) {
                    v0 += base[(size_t)row0 * ldc + col];
                    v1 += base[(size_t)row0 * ldc + col + 1];
                }
                if (act) { v0 = fmaxf(v0, 0.f); v1 = fmaxf(v1, 0.f); }
                if (roundOut) { v0 = tf32r(v0); v1 = tf32r(v1); }
                C[(size_t)row0 * ldc + col] = v0;
                C[(size_t)row0 * ldc + col + 1] = v1;
            }
            if (row1 < M) {
                float v2 = acc[am][an][2] + add0;
                float v3 = acc[am][an][3] + add1;
                if (base) {
                    v2 += base[(size_t)row1 * ldc + col];
                    v3 += base[(size_t)row1 * ldc + col + 1];
                }
                if (act) { v2 = fmaxf(v2, 0.f); v3 = fmaxf(v3, 0.f); }
                if (roundOut) { v2 = tf32r(v2); v3 = tf32r(v3); }
                C[(size_t)row1 * ldc + col] = v2;
                C[(size_t)row1 * ldc + col + 1] = v3;
            }
        }
    }
}

// ------------------- residual layernorm (tf32-rounded output) -------------------
__global__ void __launch_bounds__(256)
ln_kernel(const float* __restrict__ g, const float* __restrict__ b) {
    __shared__ float s_red[16];
    int r = blockIdx.x, t = threadIdx.x;
    float v = g_enc[(size_t)r * DM + t] + g_vec[(size_t)r * DM + t];
    float s1 = warp_sum(v), s2 = warp_sum(v * v);
    if ((t & 31) == 0) { s_red[t >> 5] = s1; s_red[8 + (t >> 5)] = s2; }
    __syncthreads();
    float S1 = 0.f, S2 = 0.f;
#pragma unroll
    for (int i = 0; i < 8; i++) { S1 += s_red[i]; S2 += s_red[8 + i]; }
    float mean = S1 * (1.0f / 256.0f);
    float var = S2 * (1.0f / 256.0f) - mean * mean;
    g_enc[(size_t)r * DM + t] = tf32r((v - mean) * rsqrtf(var + 1e-5f) * g[t] + b[t]);
}

__global__ void supmean_kernel() {
    int t = threadIdx.x;
    float s = 0.f;
#pragma unroll
    for (int i = 0; i < NSUP; i++) s += g_enc[(size_t)(NB + i) * DM + t];
    g_supg[t] = s * (1.0f / NSUP);
}

__global__ void rpart_kernel(const float* __restrict__ whh) {
    __shared__ float sg[DM];
    int t = threadIdx.x;
    sg[t] = g_supg[t];
    __syncthreads();
    int n = blockIdx.x * 256 + t;
    const float* row = whh + (size_t)n * LH + DM;
    float s = 0.f;
    for (int k = 0; k < DM; k += 4) {
        float4 w = *(const float4*)(row + k);
        s += w.x * sg[k] + w.y * sg[k + 1] + w.z * sg[k + 2] + w.w * sg[k + 3];
    }
    g_rpart[n] = s;
}

// ------------------- LSTM cell pointwise -------------------
__global__ void __launch_bounds__(256)
cell_kernel(const float* __restrict__ gates, int first) {
    int idx = blockIdx.x * 256 + threadIdx.x;
    int b = idx >> 9, u = idx & 511;
    const float* g = gates + (size_t)b * G4;
    float iv = sigf(g[u]);
    float fv = sigf(g[512 + u]);
    float gv = tanhf(g[1024 + u]);
    float ov = sigf(g[1536 + u]);
    float cp = first ? 0.f : g_c[idx];
    float cn = fv * cp + iv * gv;
    g_c[idx] = cn;
    float hh = ov * tanhf(cn);
    if (u < DM) g_h[(size_t)b * DM + u] = tf32r(g_enc[(size_t)b * DM + u] + hh);
}

// ------------------- final dot -------------------
__global__ void __launch_bounds__(256)
dot_kernel(float* __restrict__ out) {
    int warp = threadIdx.x >> 5, lane = threadIdx.x & 31;
    int b = blockIdx.x * 8 + warp;
    const float* hp = g_h + (size_t)b * DM;
    float s = 0.f;
#pragma unroll
    for (int k = 0; k < DM; k += 32) s += hp[k + lane] * g_supg[k + lane];
    s = warp_sum(s);
    if (lane == 0) out[b] = s;
}

// ------------------- host -------------------
extern "C" void kernel_launch(void* const* d_in, const int* in_sizes, int n_in,
                              void* d_out, int out_size) {
    const int* qry      = (const int*)d_in[0];
    const int* sup      = (const int*)d_in[1];
    const int* q_l1     = (const int*)d_in[2];
    const int* q_deg_l  = (const int*)d_in[3];
    const int* q_r1     = (const int*)d_in[4];
    const int* q_deg_r  = (const int*)d_in[5];
    const int* s_l1     = (const int*)d_in[6];
    const int* s_deg_l  = (const int*)d_in[7];
    const int* s_r1     = (const int*)d_in[8];
    const int* s_deg_r  = (const int*)d_in[9];
    const float* emb    = (const float*)d_in[10];
    const float* gcn_w_w = (const float*)d_in[11];
    const float* gcn_w_b = (const float*)d_in[12];
    const float* gcn_b   = (const float*)d_in[13];
    const float* g1_w    = (const float*)d_in[14];
    const float* g1_b    = (const float*)d_in[15];
    const float* ln1_g   = (const float*)d_in[16];
    const float* ln1_b   = (const float*)d_in[17];
    const float* g2_w    = (const float*)d_in[18];
    const float* g2_b    = (const float*)d_in[19];
    const float* gate_temp = (const float*)d_in[20];
    const float* se_p1_w = (const float*)d_in[21];
    const float* se_p1_b = (const float*)d_in[22];
    const float* se_p2_w = (const float*)d_in[23];
    const float* se_p2_b = (const float*)d_in[24];
    const float* se_ln_g = (const float*)d_in[25];
    const float* se_ln_b = (const float*)d_in[26];
    const float* w_ih    = (const float*)d_in[27];
    const float* w_hh    = (const float*)d_in[28];
    const float* b_ih    = (const float*)d_in[29];
    const float* b_hh    = (const float*)d_in[30];

    float *vec, *h1, *enc, *xpart, *gates, *h, *bsum, *rpart;
    float *wihR, *whhR, *p1R, *p2R;
    cudaGetSymbolAddress((void**)&vec, g_vec);
    cudaGetSymbolAddress((void**)&h1, g_h1);
    cudaGetSymbolAddress((void**)&enc, g_enc);
    cudaGetSymbolAddress((void**)&xpart, g_xpart);
    cudaGetSymbolAddress((void**)&gates, g_gates);
    cudaGetSymbolAddress((void**)&h, g_h);
    cudaGetSymbolAddress((void**)&bsum, g_bsum);
    cudaGetSymbolAddress((void**)&rpart, g_rpart);
    cudaGetSymbolAddress((void**)&wihR, g_wihR);
    cudaGetSymbolAddress((void**)&whhR, g_whhR);
    cudaGetSymbolAddress((void**)&p1R, g_p1R);
    cudaGetSymbolAddress((void**)&p2R, g_p2R);

    prep_kernel<<<136, 256>>>(gcn_w_w, b_ih, b_hh);
    round_kernel<<<(G4 * DM + 255) / 256, 256>>>(w_ih, wihR, G4 * DM);
    round_kernel<<<(G4 * LH + 255) / 256, 256>>>(w_hh, whhR, G4 * LH);
    round_kernel<<<(DI * DM + 255) / 256, 256>>>(se_p1_w, p1R, DI * DM);
    round_kernel<<<(DM * DI + 255) / 256, 256>>>(se_p2_w, p2R, DM * DI);

    neighbor_kernel<<<2 * NB + 2 * NSUP, 128>>>(
        qry, sup, q_l1, q_deg_l, q_r1, q_deg_r, s_l1, s_deg_l, s_r1, s_deg_r,
        emb, gcn_w_b, gcn_b, g1_w, g1_b, ln1_g, ln1_b, g2_w, g2_b, gate_temp);

    // support encoder on all 4101 rows (BM=64 for more CTAs)
    gemm_v2<64><<<dim3(DI / 128, (NROWS + 63) / 64), 256>>>(
        vec, DM, p1R, DM, se_p1_b, nullptr, nullptr, h1, DI, NROWS, DI, DM, 1, 1);
    gemm_v2<64><<<dim3(DM / 128, (NROWS + 63) / 64), 256>>>(
        h1, DI, p2R, DI, se_p2_b, nullptr, nullptr, enc, DM, NROWS, DM, DI, 0, 0);
    ln_kernel<<<NROWS, 256>>>(se_ln_g, se_ln_b);

    supmean_kernel<<<1, 256>>>();
    rpart_kernel<<<G4 / 256, 256>>>(w_hh);

    // xpart = query_enc @ w_ih.T + (b_ih + b_hh)
    gemm_v2<128><<<dim3(G4 / 128, NB / 128), 256>>>(
        enc, DM, wihR, DM, bsum, nullptr, nullptr, xpart, G4, NB, G4, DM, 0, 0);

    cell_kernel<<<(NB * LH) / 256, 256>>>(xpart, 1);

    for (int s = 0; s < 3; s++) {
        gemm_v2<128><<<dim3(G4 / 128, NB / 128), 256>>>(
            h, DM, whhR, LH, nullptr, xpart, rpart, gates, G4, NB, G4, DM, 0, 0);
        cell_kernel<<<(NB * LH) / 256, 256>>>(gates, 0);
    }

    dot_kernel<<<NB / 8, 256>>>((float*)d_out);
}